// round 2
// baseline (speedup 1.0000x reference)
#include <cuda_runtime.h>
#include <cuda_bf16.h>
#include <cstdint>

#define LL 65536
#define DD 256
#define CC 512      // number of chunks
#define RR 128      // rows per chunk (LL / CC)

#define NEG_INF __int_as_float(0xff800000)

// ---- scratch (device globals; no allocation allowed) ----
__device__ float g_s[LL];            // s[i] = K[i]·q
__device__ float g_M[CC], g_U[CC];   // per-chunk aggregates (U referenced to M)
__device__ float g_W[CC * DD];       // per-chunk vector aggregate (ref M_c)
__device__ float g_Mp[CC], g_Up[CC]; // exclusive prefix (Up referenced to Mp)
__device__ float g_Wp[CC * DD];      // GLOBAL exclusive W prefix (ref Mp_c)
__device__ int   g_count = 0;        // completion counter (reset by tail)

// ============================================================
// Pass 1: s = K·q ; per-chunk (M, U, W) reduction.
// Last-arriving block runs the full middle scan in-block.
// ============================================================
__global__ __launch_bounds__(256) void k_pass1(const float* __restrict__ K,
                                               const float* __restrict__ V,
                                               const float* __restrict__ q) {
    __shared__ float q_sh[DD];
    __shared__ float s_sh[RR];
    __shared__ float e_sh[RR];
    __shared__ float red_sh[8];
    __shared__ float wpart[4][DD];
    __shared__ float Mbc;
    __shared__ int amLast;
    // tail-stage shared (only used by the last block)
    __shared__ float Pm[CC];
    __shared__ float alsh[CC];
    __shared__ float gash[CC];
    __shared__ float besh[CC];

    const int c = blockIdx.x;
    const int t = threadIdx.x;
    const int lane = t & 31;
    const int wid = t >> 5;

    q_sh[t] = q[t];
    __syncthreads();

    const float4* q4 = reinterpret_cast<const float4*>(q_sh);
    const float4* K4 = reinterpret_cast<const float4*>(K) + (size_t)c * RR * (DD / 4);

    // --- s for this chunk: 8 warps x 16 rows ---
    float4 qa = q4[lane], qb = q4[32 + lane];
    for (int k = 0; k < 16; k++) {
        int r = wid * 16 + k;
        float4 ka = K4[r * 64 + lane];
        float4 kb = K4[r * 64 + 32 + lane];
        float p = ka.x * qa.x + ka.y * qa.y + ka.z * qa.z + ka.w * qa.w
                + kb.x * qb.x + kb.y * qb.y + kb.z * qb.z + kb.w * qb.w;
#pragma unroll
        for (int o = 16; o; o >>= 1) p += __shfl_xor_sync(0xffffffffu, p, o);
        if (lane == 0) s_sh[r] = p;
    }
    __syncthreads();

    if (t < RR) g_s[c * RR + t] = s_sh[t];

    // --- chunk max M ---
    float m = (t < RR) ? s_sh[t] : NEG_INF;
#pragma unroll
    for (int o = 16; o; o >>= 1) m = fmaxf(m, __shfl_xor_sync(0xffffffffu, m, o));
    if (lane == 0) red_sh[wid] = m;
    __syncthreads();
    if (t == 0) {
        float mm = NEG_INF;
#pragma unroll
        for (int w = 0; w < 8; w++) mm = fmaxf(mm, red_sh[w]);
        Mbc = mm;
    }
    __syncthreads();
    const float M = Mbc;

    if (t < RR) e_sh[t] = __expf(s_sh[t] - M);
    __syncthreads();

    // --- U = sum e ---
    float uu = (t < RR) ? e_sh[t] : 0.f;
#pragma unroll
    for (int o = 16; o; o >>= 1) uu += __shfl_xor_sync(0xffffffffu, uu, o);
    __syncthreads();
    if (lane == 0) red_sh[wid] = uu;
    __syncthreads();
    if (t == 0) {
        float U = 0.f;
#pragma unroll
        for (int w = 0; w < 8; w++) U += red_sh[w];
        g_M[c] = M;
        g_U[c] = U;
    }

    // --- W[d] = sum_i e_i * V[i][d] ---
    const int grp = t >> 6;
    const int j = t & 63;
    const float4* V4 = reinterpret_cast<const float4*>(V) + (size_t)c * RR * 64;
    float4 acc = make_float4(0.f, 0.f, 0.f, 0.f);
#pragma unroll 8
    for (int i = grp; i < RR; i += 4) {
        float e = e_sh[i];
        float4 v = V4[i * 64 + j];
        acc.x += e * v.x; acc.y += e * v.y; acc.z += e * v.z; acc.w += e * v.w;
    }
    reinterpret_cast<float4*>(wpart[grp])[j] = acc;
    __syncthreads();
    float W = wpart[0][t] + wpart[1][t] + wpart[2][t] + wpart[3][t];
    g_W[(size_t)c * DD + t] = W;

    // ======== completion detection ========
    __threadfence();
    if (t == 0) {
        int prev = atomicAdd(&g_count, 1);
        amLast = (prev == CC - 1);
    }
    __syncthreads();
    if (!amLast) return;

    // ======== TAIL: middle scan, run by the last block only ========
    // scalar: prefix max over chunk maxima
    float m0 = __ldcg(&g_M[t]);
    float m1 = __ldcg(&g_M[t + 256]);
    Pm[t] = m0; Pm[t + 256] = m1;
    __syncthreads();

    float c0 = Pm[t], c1 = Pm[t + 256];
    for (int off = 1; off < CC; off <<= 1) {
        float v0 = (t >= off) ? Pm[t - off] : NEG_INF;
        float v1 = (t + 256 >= off) ? Pm[t + 256 - off] : NEG_INF;
        __syncthreads();
        c0 = fmaxf(c0, v0); c1 = fmaxf(c1, v1);
        Pm[t] = c0; Pm[t + 256] = c1;
        __syncthreads();
    }

#pragma unroll
    for (int r = 0; r < 2; r++) {
        int i = t + r * 256;
        float Minc = Pm[i];
        float Mp = (i == 0) ? NEG_INF : Pm[i - 1];
        float a = (i == 0) ? 0.f : __expf(Mp - Minc);
        float g = __expf(((r == 0) ? m0 : m1) - Minc);
        alsh[i] = a;
        gash[i] = g;
        besh[i] = __ldcg(&g_U[i]) * g;
        g_Mp[i] = Mp;
    }
    __syncthreads();

    // serial u-scan (exclusive, ref Mp_c) by thread 0
    if (t == 0) {
        float u = 0.f;
#pragma unroll 8
        for (int cix = 0; cix < CC; cix++) {
            g_Up[cix] = u;
            u = fmaf(u, alsh[cix], besh[cix]);
        }
    }

    // full W-prefix scan: thread t owns dim t (g_W is L2-hot)
    {
        float w = 0.f;
#pragma unroll 8
        for (int jx = 0; jx < CC; jx++) {
            float wc = __ldcg(&g_W[(size_t)jx * DD + t]);
            g_Wp[(size_t)jx * DD + t] = w;
            w = fmaf(w, alsh[jx], wc * gash[jx]);
        }
    }

    if (t == 0) g_count = 0;   // reset for next graph replay
}

// ============================================================
// Pass 2: rebuild per-row recurrence, stream V -> out.
// Processes chunks in REVERSE order so the L2-resident V tail
// (left over from pass 1) is consumed before self-eviction.
// ============================================================
__global__ __launch_bounds__(256) void k_pass2(const float* __restrict__ V,
                                               float* __restrict__ out) {
    __shared__ float s_loc[RR], m_sh[RR];
    __shared__ float a_sh[RR], b_sh[RR];
    __shared__ float u_sh[RR], inv_sh[RR];

    const int c = (CC - 1) - blockIdx.x;
    const int t = threadIdx.x;

    const float Mp_c = g_Mp[c];
    const float Up_c = g_Up[c];

    if (t < RR) {
        float sv = g_s[c * RR + t];
        s_loc[t] = sv;
        m_sh[t] = sv;
    }
    __syncthreads();

    // inclusive prefix max over s within the chunk
#pragma unroll
    for (int off = 1; off < RR; off <<= 1) {
        float v = NEG_INF;
        if (t < RR && t >= off) v = m_sh[t - off];
        __syncthreads();
        if (t < RR) m_sh[t] = fmaxf(m_sh[t], v);
        __syncthreads();
    }

    if (t < RR) {
        float mi = fmaxf(m_sh[t], Mp_c);
        float mp = (t == 0) ? Mp_c : fmaxf(m_sh[t - 1], Mp_c);
        a_sh[t] = __expf(mp - mi);            // exp(-inf - finite) = 0 : safe
        b_sh[t] = __expf(s_loc[t] - mi);
    }
    __syncthreads();

    if (t == 0) {
        float u = Up_c;
#pragma unroll 8
        for (int i = 0; i < RR; i++) {
            u = fmaf(u, a_sh[i], b_sh[i]);
            u_sh[i] = u;
        }
    }
    __syncthreads();
    if (t < RR) inv_sh[t] = 1.0f / u_sh[t];
    __syncthreads();

    // seed: global exclusive W prefix, already referenced to Mp_c
    float w = g_Wp[(size_t)c * DD + t];

    const float* Vb = V + (size_t)c * RR * DD + t;
    float* Ob = out + (size_t)c * RR * DD + t;

    float cur[8];
#pragma unroll
    for (int j = 0; j < 8; j++) cur[j] = Vb[(size_t)j * DD];

    for (int ib = 0; ib < RR; ib += 8) {
        float nxt[8];
#pragma unroll
        for (int j = 0; j < 8; j++)
            nxt[j] = (ib + 8 < RR) ? Vb[(size_t)(ib + 8 + j) * DD] : 0.f;
#pragma unroll
        for (int j = 0; j < 8; j++) {
            int i = ib + j;
            w = fmaf(w, a_sh[i], b_sh[i] * cur[j]);
            Ob[(size_t)i * DD] = w * inv_sh[i];
        }
#pragma unroll
        for (int j = 0; j < 8; j++) cur[j] = nxt[j];
    }
}

// ============================================================
extern "C" void kernel_launch(void* const* d_in, const int* in_sizes, int n_in,
                              void* d_out, int out_size) {
    const float* K = (const float*)d_in[0];
    const float* V = (const float*)d_in[1];
    const float* q = (const float*)d_in[2];
    float* out = (float*)d_out;

    k_pass1<<<CC, 256>>>(K, V, q);
    k_pass2<<<CC, 256>>>(V, out);
}

// round 3
// speedup vs baseline: 1.5662x; 1.5662x over previous
#include <cuda_runtime.h>
#include <cuda_bf16.h>
#include <cstdint>

#define LL 65536
#define DD 256
#define CC 1024     // number of chunks
#define RR 64       // rows per chunk
#define NSEG 16     // segments
#define SEGC 64     // chunks per segment (CC / NSEG)

#define NEG_INF __int_as_float(0xff800000)

// ---- scratch (device globals) ----
__device__ float g_s[LL];            // s[i] = K[i]·q
__device__ float g_M[CC], g_U[CC];   // per-chunk aggregates (U ref M)
__device__ float g_W[CC * DD];       // per-chunk vector aggregate (ref M_c)
__device__ float g_Mp[CC], g_Up[CC]; // exclusive prefix (Up ref Mp)
__device__ float g_Wp[CC * DD];      // segment-local exclusive W prefix (ref Mp_c)
__device__ float g_seg[NSEG * DD];   // segment aggregates (ref Mp[(b+1)*SEGC])

// ============================================================
// Pass 1: s = K·q ; per-chunk (M, U, W) reduction
// ============================================================
__global__ __launch_bounds__(256) void k_pass1(const float* __restrict__ K,
                                               const float* __restrict__ V,
                                               const float* __restrict__ q) {
    __shared__ float q_sh[DD];
    __shared__ float s_sh[RR];
    __shared__ float e_sh[RR];
    __shared__ float red_sh[8];
    __shared__ float wpart[4][DD];
    __shared__ float Mbc;

    const int c = blockIdx.x;
    const int t = threadIdx.x;
    const int lane = t & 31;
    const int wid = t >> 5;

    q_sh[t] = q[t];
    __syncthreads();

    const float4* q4 = reinterpret_cast<const float4*>(q_sh);
    const float4* K4 = reinterpret_cast<const float4*>(K) + (size_t)c * RR * (DD / 4);

    // --- s: 8 warps x 8 rows, one warp per row ---
    float4 qa = q4[lane], qb = q4[32 + lane];
#pragma unroll
    for (int k = 0; k < RR / 8; k++) {
        int r = wid * (RR / 8) + k;
        float4 ka = __ldcs(&K4[r * 64 + lane]);        // K read-once: evict-first
        float4 kb = __ldcs(&K4[r * 64 + 32 + lane]);
        float p = ka.x * qa.x + ka.y * qa.y + ka.z * qa.z + ka.w * qa.w
                + kb.x * qb.x + kb.y * qb.y + kb.z * qb.z + kb.w * qb.w;
#pragma unroll
        for (int o = 16; o; o >>= 1) p += __shfl_xor_sync(0xffffffffu, p, o);
        if (lane == 0) s_sh[r] = p;
    }
    __syncthreads();

    if (t < RR) g_s[c * RR + t] = s_sh[t];

    // --- chunk max M ---
    float m = (t < RR) ? s_sh[t] : NEG_INF;
#pragma unroll
    for (int o = 16; o; o >>= 1) m = fmaxf(m, __shfl_xor_sync(0xffffffffu, m, o));
    if (lane == 0) red_sh[wid] = m;
    __syncthreads();
    if (t == 0) {
        float mm = NEG_INF;
#pragma unroll
        for (int w = 0; w < 8; w++) mm = fmaxf(mm, red_sh[w]);
        Mbc = mm;
    }
    __syncthreads();
    const float M = Mbc;

    if (t < RR) e_sh[t] = __expf(s_sh[t] - M);
    __syncthreads();

    // --- U = sum e ---
    float uu = (t < RR) ? e_sh[t] : 0.f;
#pragma unroll
    for (int o = 16; o; o >>= 1) uu += __shfl_xor_sync(0xffffffffu, uu, o);
    __syncthreads();
    if (lane == 0) red_sh[wid] = uu;
    __syncthreads();
    if (t == 0) {
        float U = 0.f;
#pragma unroll
        for (int w = 0; w < 8; w++) U += red_sh[w];
        g_M[c] = M;
        g_U[c] = U;
    }

    // --- W[d] = sum_i e_i * V[i][d] ---
    const int grp = t >> 6;
    const int j = t & 63;
    const float4* V4 = reinterpret_cast<const float4*>(V) + (size_t)c * RR * 64;
    float4 acc = make_float4(0.f, 0.f, 0.f, 0.f);
#pragma unroll
    for (int i = grp; i < RR; i += 4) {
        float e = e_sh[i];
        float4 v = V4[i * 64 + j];
        acc.x += e * v.x; acc.y += e * v.y; acc.z += e * v.z; acc.w += e * v.w;
    }
    reinterpret_cast<float4*>(wpart[grp])[j] = acc;
    __syncthreads();
    float W = wpart[0][t] + wpart[1][t] + wpart[2][t] + wpart[3][t];
    g_W[(size_t)c * DD + t] = W;
}

// ============================================================
// Mid kernel: NSEG blocks. Every block redundantly computes the
// scalar prefix (cheap); block b does the register-resident
// segment W-scan for chunks [b*SEGC, (b+1)*SEGC). Block 0 also
// writes g_Mp and does the serial u-scan.
// ============================================================
__global__ __launch_bounds__(256) void k_mid() {
    __shared__ float Pm[CC];                  // 4KB
    __shared__ float alsh[CC];                // 4KB
    __shared__ float gash[CC];                // 4KB
    __shared__ float besh[CC];                // 4KB (block 0 u-scan)
    __shared__ float ush[CC];                 // 4KB (block 0 u-scan out)

    const int b = blockIdx.x;
    const int t = threadIdx.x;

    float mv[4];
#pragma unroll
    for (int r = 0; r < 4; r++) {
        mv[r] = g_M[t + r * 256];
        Pm[t + r * 256] = mv[r];
    }
    __syncthreads();

    // inclusive prefix max (Hillis-Steele), 4 elems/thread
    for (int off = 1; off < CC; off <<= 1) {
        float v[4];
#pragma unroll
        for (int r = 0; r < 4; r++) {
            int i = t + r * 256;
            v[r] = (i >= off) ? Pm[i - off] : NEG_INF;
        }
        __syncthreads();
#pragma unroll
        for (int r = 0; r < 4; r++) {
            int i = t + r * 256;
            Pm[i] = fmaxf(Pm[i], v[r]);
        }
        __syncthreads();
    }

#pragma unroll
    for (int r = 0; r < 4; r++) {
        int i = t + r * 256;
        float Minc = Pm[i];
        float Mp = (i == 0) ? NEG_INF : Pm[i - 1];
        float a = (i == 0) ? 0.f : __expf(Mp - Minc);
        float g = __expf(mv[r] - Minc);
        alsh[i] = a;
        gash[i] = g;
        besh[i] = g_U[i] * g;
        if (b == 0) g_Mp[i] = Mp;
    }
    __syncthreads();

    // block 0: serial u-scan into shared, then parallel store
    if (b == 0) {
        if (t == 0) {
            float u = 0.f;
#pragma unroll 8
            for (int cix = 0; cix < CC; cix++) {
                ush[cix] = u;                  // exclusive, ref Mp_c
                u = fmaf(u, alsh[cix], besh[cix]);
            }
        }
        __syncthreads();
#pragma unroll
        for (int r = 0; r < 4; r++) g_Up[t + r * 256] = ush[t + r * 256];
    }

    // segment W-scan, register-resident
    const int j0 = b * SEGC;
    const float* Wsrc = g_W + (size_t)j0 * DD + t;
    float* Wdst = g_Wp + (size_t)j0 * DD + t;

    float wc[SEGC];
#pragma unroll
    for (int j = 0; j < SEGC; j++) wc[j] = Wsrc[(size_t)j * DD];

    float w = 0.f;
#pragma unroll
    for (int j = 0; j < SEGC; j++) {
        Wdst[(size_t)j * DD] = w;              // exclusive within segment, ref Mp_c
        w = fmaf(w, alsh[j0 + j], wc[j] * gash[j0 + j]);
    }
    g_seg[b * DD + t] = w;                     // ref Mp[(b+1)*SEGC]
}

// ============================================================
// Pass 2: rebuild per-row recurrence, stream V -> out.
// Reverse chunk order for L2 reuse of the V tail from pass 1.
// Each block reconstructs its segment carry from g_seg.
// ============================================================
__global__ __launch_bounds__(256) void k_pass2(const float* __restrict__ V,
                                               float* __restrict__ out) {
    __shared__ float s_loc[RR], m_sh[RR];
    __shared__ float a_sh[RR], b_sh[RR];
    __shared__ float u_sh[RR], inv_sh[RR];

    const int c = (CC - 1) - blockIdx.x;
    const int t = threadIdx.x;

    const float Mp_c = g_Mp[c];
    const float Up_c = g_Up[c];

    if (t < RR) {
        float sv = g_s[c * RR + t];
        s_loc[t] = sv;
        m_sh[t] = sv;
    }
    __syncthreads();

    // inclusive prefix max over s within the chunk
#pragma unroll
    for (int off = 1; off < RR; off <<= 1) {
        float v = NEG_INF;
        if (t < RR && t >= off) v = m_sh[t - off];
        __syncthreads();
        if (t < RR) m_sh[t] = fmaxf(m_sh[t], v);
        __syncthreads();
    }

    if (t < RR) {
        float mi = fmaxf(m_sh[t], Mp_c);
        float mp = (t == 0) ? Mp_c : fmaxf(m_sh[t - 1], Mp_c);
        a_sh[t] = __expf(mp - mi);            // exp(-inf - finite) = 0 : safe
        b_sh[t] = __expf(s_loc[t] - mi);
    }
    __syncthreads();

    if (t == 0) {
        float u = Up_c;
#pragma unroll 8
        for (int i = 0; i < RR; i++) {
            u = fmaf(u, a_sh[i], b_sh[i]);
            u_sh[i] = u;
        }
    }
    __syncthreads();
    if (t < RR) inv_sh[t] = 1.0f / u_sh[t];
    __syncthreads();

    // seed: segment-local exclusive prefix + reconstructed carry
    const int seg = c / SEGC;
    float w = g_Wp[(size_t)c * DD + t];
    if (seg > 0) {
        float car = 0.f;
        for (int sb = 0; sb < seg; sb++) {
            float sc = (sb == 0) ? 0.f
                     : __expf(g_Mp[sb * SEGC] - g_Mp[(sb + 1) * SEGC]);
            car = fmaf(car, sc, g_seg[sb * DD + t]);
        }
        // car is ref Mp[seg*SEGC]; rescale to Mp_c
        w = fmaf(car, __expf(g_Mp[seg * SEGC] - Mp_c), w);
    }

    const float* Vb = V + (size_t)c * RR * DD + t;
    float* Ob = out + (size_t)c * RR * DD + t;

    float cur[8];
#pragma unroll
    for (int j = 0; j < 8; j++) cur[j] = Vb[(size_t)j * DD];

    for (int ib = 0; ib < RR; ib += 8) {
        float nxt[8];
#pragma unroll
        for (int j = 0; j < 8; j++)
            nxt[j] = (ib + 8 < RR) ? Vb[(size_t)(ib + 8 + j) * DD] : 0.f;
#pragma unroll
        for (int j = 0; j < 8; j++) {
            int i = ib + j;
            w = fmaf(w, a_sh[i], b_sh[i] * cur[j]);
            __stcs(&Ob[(size_t)i * DD], w * inv_sh[i]);   // write-once: stream
        }
#pragma unroll
        for (int j = 0; j < 8; j++) cur[j] = nxt[j];
    }
}

// ============================================================
extern "C" void kernel_launch(void* const* d_in, const int* in_sizes, int n_in,
                              void* d_out, int out_size) {
    const float* K = (const float*)d_in[0];
    const float* V = (const float*)d_in[1];
    const float* q = (const float*)d_in[2];
    float* out = (float*)d_out;

    k_pass1<<<CC, 256>>>(K, V, q);
    k_mid<<<NSEG, 256>>>();
    k_pass2<<<CC, 256>>>(V, out);
}

// round 4
// speedup vs baseline: 2.2750x; 1.4526x over previous
#include <cuda_runtime.h>
#include <cuda_bf16.h>
#include <cstdint>

#define LL 65536
#define DD 256
#define CC 1024     // number of chunks
#define RR 64       // rows per chunk
#define NSEG 16     // segments
#define SEGC 64     // chunks per segment (CC / NSEG)

#define NEG_INF __int_as_float(0xff800000)

// ---- scratch (device globals) ----
__device__ float g_s[LL];            // s[i] = K[i]·q
__device__ float g_M[CC], g_U[CC];   // per-chunk aggregates (U ref M)
__device__ float g_W[CC * DD];       // per-chunk vector aggregate (ref M_c)
__device__ float g_Mp[CC], g_Up[CC]; // exclusive prefix (Up ref Mp)
__device__ float g_Wp[CC * DD];      // segment-local exclusive W prefix (ref Mp_c)
__device__ float g_seg[NSEG * DD];   // segment aggregates (ref Mp[(b+1)*SEGC])

// ============================================================
// Pass 1: s = K·q ; per-chunk (M, U, W) reduction
// ============================================================
__global__ __launch_bounds__(256, 8) void k_pass1(const float* __restrict__ K,
                                                  const float* __restrict__ V,
                                                  const float* __restrict__ q) {
    __shared__ float q_sh[DD];
    __shared__ float s_sh[RR];
    __shared__ float e_sh[RR];
    __shared__ float red_sh[8];
    __shared__ float wpart[4][DD];
    __shared__ float Mbc;

    const int c = blockIdx.x;
    const int t = threadIdx.x;
    const int lane = t & 31;
    const int wid = t >> 5;

    q_sh[t] = q[t];
    __syncthreads();

    const float4* q4 = reinterpret_cast<const float4*>(q_sh);
    const float4* K4 = reinterpret_cast<const float4*>(K) + (size_t)c * RR * (DD / 4);

    // --- s: 8 warps x 8 rows, one warp per row ---
    float4 qa = q4[lane], qb = q4[32 + lane];
#pragma unroll
    for (int k = 0; k < RR / 8; k++) {
        int r = wid * (RR / 8) + k;
        float4 ka = __ldcs(&K4[r * 64 + lane]);        // K read-once: evict-first
        float4 kb = __ldcs(&K4[r * 64 + 32 + lane]);
        float p = ka.x * qa.x + ka.y * qa.y + ka.z * qa.z + ka.w * qa.w
                + kb.x * qb.x + kb.y * qb.y + kb.z * qb.z + kb.w * qb.w;
#pragma unroll
        for (int o = 16; o; o >>= 1) p += __shfl_xor_sync(0xffffffffu, p, o);
        if (lane == 0) s_sh[r] = p;
    }
    __syncthreads();

    if (t < RR) g_s[c * RR + t] = s_sh[t];

    // --- chunk max M ---
    float m = (t < RR) ? s_sh[t] : NEG_INF;
#pragma unroll
    for (int o = 16; o; o >>= 1) m = fmaxf(m, __shfl_xor_sync(0xffffffffu, m, o));
    if (lane == 0) red_sh[wid] = m;
    __syncthreads();
    if (t == 0) {
        float mm = NEG_INF;
#pragma unroll
        for (int w = 0; w < 8; w++) mm = fmaxf(mm, red_sh[w]);
        Mbc = mm;
    }
    __syncthreads();
    const float M = Mbc;

    if (t < RR) e_sh[t] = __expf(s_sh[t] - M);
    __syncthreads();

    // --- U = sum e ---
    float uu = (t < RR) ? e_sh[t] : 0.f;
#pragma unroll
    for (int o = 16; o; o >>= 1) uu += __shfl_xor_sync(0xffffffffu, uu, o);
    __syncthreads();
    if (lane == 0) red_sh[wid] = uu;
    __syncthreads();
    if (t == 0) {
        float U = 0.f;
#pragma unroll
        for (int w = 0; w < 8; w++) U += red_sh[w];
        g_M[c] = M;
        g_U[c] = U;
    }

    // --- W[d] = sum_i e_i * V[i][d] ---
    const int grp = t >> 6;
    const int j = t & 63;
    const float4* V4 = reinterpret_cast<const float4*>(V) + (size_t)c * RR * 64;
    float4 acc = make_float4(0.f, 0.f, 0.f, 0.f);
#pragma unroll
    for (int i = grp; i < RR; i += 4) {
        float e = e_sh[i];
        float4 v = V4[i * 64 + j];
        acc.x += e * v.x; acc.y += e * v.y; acc.z += e * v.z; acc.w += e * v.w;
    }
    reinterpret_cast<float4*>(wpart[grp])[j] = acc;
    __syncthreads();
    float W = wpart[0][t] + wpart[1][t] + wpart[2][t] + wpart[3][t];
    g_W[(size_t)c * DD + t] = W;
}

// ============================================================
// Mid kernel: NSEG blocks. Every block redundantly computes the
// scalar prefixes (max-scan + pair-scan for u, all parallel);
// block b does the register-resident segment W-scan for its
// chunks. Block 0 publishes g_Mp / g_Up.
// ============================================================
__global__ __launch_bounds__(256) void k_mid() {
    __shared__ float Pm[CC];                  // prefix max
    __shared__ float alsh[CC];                // alpha
    __shared__ float gash[CC];                // gamma
    __shared__ float As[CC];                  // pair-scan A
    __shared__ float Bs[CC];                  // pair-scan B

    const int b = blockIdx.x;
    const int t = threadIdx.x;

    float mv[4];
#pragma unroll
    for (int r = 0; r < 4; r++) {
        mv[r] = g_M[t + r * 256];
        Pm[t + r * 256] = mv[r];
    }
    __syncthreads();

    // inclusive prefix max (Hillis-Steele), 4 elems/thread
    float cm[4];
#pragma unroll
    for (int r = 0; r < 4; r++) cm[r] = mv[r];
    for (int off = 1; off < CC; off <<= 1) {
        float v[4];
#pragma unroll
        for (int r = 0; r < 4; r++) {
            int i = t + r * 256;
            v[r] = (i >= off) ? Pm[i - off] : NEG_INF;
        }
        __syncthreads();
#pragma unroll
        for (int r = 0; r < 4; r++) {
            cm[r] = fmaxf(cm[r], v[r]);
            Pm[t + r * 256] = cm[r];
        }
        __syncthreads();
    }

    float ca[4], cb[4];
#pragma unroll
    for (int r = 0; r < 4; r++) {
        int i = t + r * 256;
        float Minc = Pm[i];
        float Mp = (i == 0) ? NEG_INF : Pm[i - 1];
        float a = (i == 0) ? 0.f : __expf(Mp - Minc);
        float g = __expf(mv[r] - Minc);
        alsh[i] = a;
        gash[i] = g;
        ca[r] = a;
        cb[r] = g_U[i] * g;
        As[i] = ca[r];
        Bs[i] = cb[r];
        if (b == 0) g_Mp[i] = Mp;
    }
    __syncthreads();

    // inclusive pair scan for u: (a,b) = (al*a, bl*a + b)
    for (int off = 1; off < CC; off <<= 1) {
        float va[4], vb[4];
#pragma unroll
        for (int r = 0; r < 4; r++) {
            int i = t + r * 256;
            if (i >= off) { va[r] = As[i - off]; vb[r] = Bs[i - off]; }
            else          { va[r] = 1.f;         vb[r] = 0.f; }
        }
        __syncthreads();
#pragma unroll
        for (int r = 0; r < 4; r++) {
            int i = t + r * 256;
            cb[r] = fmaf(vb[r], ca[r], cb[r]);
            ca[r] = va[r] * ca[r];
            As[i] = ca[r];
            Bs[i] = cb[r];
        }
        __syncthreads();
    }

    if (b == 0) {
#pragma unroll
        for (int r = 0; r < 4; r++) {
            int i = t + r * 256;
            g_Up[i] = (i == 0) ? 0.f : Bs[i - 1];   // exclusive, ref Mp_i
        }
    }

    // segment W-scan, register-resident
    const int j0 = b * SEGC;
    const float* Wsrc = g_W + (size_t)j0 * DD + t;
    float* Wdst = g_Wp + (size_t)j0 * DD + t;

    float wc[SEGC];
#pragma unroll
    for (int j = 0; j < SEGC; j++) wc[j] = Wsrc[(size_t)j * DD];

    float w = 0.f;
#pragma unroll
    for (int j = 0; j < SEGC; j++) {
        Wdst[(size_t)j * DD] = w;              // exclusive within segment, ref Mp_c
        w = fmaf(w, alsh[j0 + j], wc[j] * gash[j0 + j]);
    }
    g_seg[b * DD + t] = w;                     // ref Mp[(b+1)*SEGC]
}

// ============================================================
// Pass 2: rebuild per-row recurrence (all scans parallel),
// stream V -> out. Reverse chunk order for L2 reuse.
// ============================================================
__global__ __launch_bounds__(256, 8) void k_pass2(const float* __restrict__ V,
                                                  float* __restrict__ out) {
    __shared__ float s_loc[RR], m_sh[RR];
    __shared__ float a_sh[RR], b_sh[RR];
    __shared__ float sA[RR], sB[RR];
    __shared__ float inv_sh[RR];

    const int c = (CC - 1) - blockIdx.x;
    const int t = threadIdx.x;

    const float Mp_c = g_Mp[c];
    const float Up_c = g_Up[c];

    if (t < RR) {
        float sv = g_s[c * RR + t];
        s_loc[t] = sv;
        m_sh[t] = sv;
    }
    __syncthreads();

    // inclusive prefix max over s within the chunk
    float cmx = (t < RR) ? m_sh[t] : NEG_INF;
#pragma unroll
    for (int off = 1; off < RR; off <<= 1) {
        float v = NEG_INF;
        if (t < RR && t >= off) v = m_sh[t - off];
        __syncthreads();
        if (t < RR) { cmx = fmaxf(cmx, v); m_sh[t] = cmx; }
        __syncthreads();
    }

    float cA = 1.f, cB = 0.f;
    if (t < RR) {
        float mi = fmaxf(m_sh[t], Mp_c);
        float mp = (t == 0) ? Mp_c : fmaxf(m_sh[t - 1], Mp_c);
        float a = __expf(mp - mi);            // exp(-inf - finite) = 0 : safe
        float bb = __expf(s_loc[t] - mi);
        a_sh[t] = a;
        b_sh[t] = bb;
        cA = a; cB = bb;
        sA[t] = a; sB[t] = bb;
    }
    __syncthreads();

    // inclusive pair scan: u_i = B_i + A_i * Up_c
#pragma unroll
    for (int off = 1; off < RR; off <<= 1) {
        float va = 1.f, vb = 0.f;
        if (t < RR && t >= off) { va = sA[t - off]; vb = sB[t - off]; }
        __syncthreads();
        if (t < RR) {
            cB = fmaf(vb, cA, cB);
            cA = va * cA;
            sA[t] = cA; sB[t] = cB;
        }
        __syncthreads();
    }
    if (t < RR) inv_sh[t] = 1.0f / fmaf(cA, Up_c, cB);
    __syncthreads();

    // seed: segment-local exclusive prefix + reconstructed carry
    const int seg = c / SEGC;
    float w = g_Wp[(size_t)c * DD + t];
    if (seg > 0) {
        float car = 0.f;
        for (int sb = 0; sb < seg; sb++) {
            float sc = (sb == 0) ? 0.f
                     : __expf(g_Mp[sb * SEGC] - g_Mp[(sb + 1) * SEGC]);
            car = fmaf(car, sc, g_seg[sb * DD + t]);
        }
        // car is ref Mp[seg*SEGC]; rescale to Mp_c
        w = fmaf(car, __expf(g_Mp[seg * SEGC] - Mp_c), w);
    }

    const float* Vb = V + (size_t)c * RR * DD + t;
    float* Ob = out + (size_t)c * RR * DD + t;

    float cur[8];
#pragma unroll
    for (int j = 0; j < 8; j++) cur[j] = Vb[(size_t)j * DD];

    for (int ib = 0; ib < RR; ib += 8) {
        float nxt[8];
#pragma unroll
        for (int j = 0; j < 8; j++)
            nxt[j] = (ib + 8 < RR) ? Vb[(size_t)(ib + 8 + j) * DD] : 0.f;
#pragma unroll
        for (int j = 0; j < 8; j++) {
            int i = ib + j;
            w = fmaf(w, a_sh[i], b_sh[i] * cur[j]);
            __stcs(&Ob[(size_t)i * DD], w * inv_sh[i]);   // write-once: stream
        }
#pragma unroll
        for (int j = 0; j < 8; j++) cur[j] = nxt[j];
    }
}

// ============================================================
extern "C" void kernel_launch(void* const* d_in, const int* in_sizes, int n_in,
                              void* d_out, int out_size) {
    const float* K = (const float*)d_in[0];
    const float* V = (const float*)d_in[1];
    const float* q = (const float*)d_in[2];
    float* out = (float*)d_out;

    k_pass1<<<CC, 256>>>(K, V, q);
    k_mid<<<NSEG, 256>>>();
    k_pass2<<<CC, 256>>>(V, out);
}